// round 9
// baseline (speedup 1.0000x reference)
#include <cuda_runtime.h>
#include <cstdint>

// YOLO loss: pred/target (bs, 7, 7, 30) f32 -> scalar f32.
// R6 pipeline (cp.async.bulk 4-stage ring, single-thread issue, mbarrier
// completion, one __syncthreads per tile) + CONTIGUOUS tile ownership:
// each CTA streams a sequential ~1.3MB range of each tensor, so every bulk
// copy continues at the previous one's end address (DRAM row locality).

#define S_GRID 7
#define CH 30
#define TILE 96
#define NTHREADS 128
#define STAGES 4
#define SFLOATS (TILE * CH)                 // 2880 floats per tensor per stage
#define STAGE_FLOATS (2 * SFLOATS)          // 5760 floats (pred + targ)
#define STAGE_BYTES (STAGE_FLOATS * 4)      // 23040 B
#define HALF_BYTES (SFLOATS * 4)            // 11520 B
#define SMEM_BYTES (STAGES * STAGE_BYTES)   // 92160 B -> 2 CTAs/SM
#define MAX_BLOCKS 296                      // 2 * 148

__device__ double g_acc = 0.0;
__device__ unsigned int g_counter = 0u;

__device__ __forceinline__ void mbar_init(uint32_t mbar, uint32_t cnt) {
    asm volatile("mbarrier.init.shared.b64 [%0], %1;" :: "r"(mbar), "r"(cnt) : "memory");
}
__device__ __forceinline__ void mbar_expect_tx(uint32_t mbar, uint32_t bytes) {
    asm volatile("mbarrier.arrive.expect_tx.shared.b64 _, [%0], %1;"
                 :: "r"(mbar), "r"(bytes) : "memory");
}
__device__ __forceinline__ void mbar_wait(uint32_t mbar, uint32_t parity) {
    asm volatile(
        "{\n\t"
        ".reg .pred P;\n\t"
        "WAIT_%=:\n\t"
        "mbarrier.try_wait.parity.acquire.cta.shared::cta.b64 P, [%0], %1, 0x989680;\n\t"
        "@P bra.uni DONE_%=;\n\t"
        "bra.uni WAIT_%=;\n\t"
        "DONE_%=:\n\t"
        "}" :: "r"(mbar), "r"(parity) : "memory");
}
__device__ __forceinline__ void bulk_g2s(uint32_t dst, const void* src,
                                         uint32_t bytes, uint32_t mbar) {
    asm volatile(
        "cp.async.bulk.shared::cta.global.mbarrier::complete_tx::bytes [%0], [%1], %2, [%3];"
        :: "r"(dst), "l"(src), "r"(bytes), "r"(mbar) : "memory");
}

// Issue one tile (pred+targ halves) into a stage; called by tid 0 only.
__device__ __forceinline__ void issue_tile_bulk(uint32_t smem_u32, int stage,
                                                uint32_t mbar,
                                                const char* __restrict__ pred,
                                                const char* __restrict__ targ,
                                                long long tile) {
    const uint32_t dst = smem_u32 + (uint32_t)stage * STAGE_BYTES;
    mbar_expect_tx(mbar, STAGE_BYTES);
    bulk_g2s(dst,              pred + tile * (long long)HALF_BYTES, HALF_BYTES, mbar);
    bulk_g2s(dst + HALF_BYTES, targ + tile * (long long)HALF_BYTES, HALF_BYTES, mbar);
}

// Per-cell loss; p/t point at 30 contiguous floats (smem or gmem).
__device__ __forceinline__ float cell_loss(const float* __restrict__ p,
                                           const float* __restrict__ t)
{
    const float obj = (t[4] > 0.0f) ? 1.0f : 0.0f;

    const float dn0 = p[4] - t[4];
    const float dn1 = p[9] - t[9];
    const float noobj = dn0 * dn0 + dn1 * dn1;

    float cls = 0.0f;
    #pragma unroll
    for (int k = 10; k < 30; k++) {
        const float d = p[k] - t[k];
        cls = fmaf(d, d, cls);
    }

    const float invS = 1.0f / (float)S_GRID;
    const float tx = t[0] * invS, ty = t[1] * invS;
    const float tw = t[2], th = t[3];
    const float tx0 = tx - 0.5f * tw, tx1 = tx + 0.5f * tw;
    const float ty0 = ty - 0.5f * th, ty1 = ty + 0.5f * th;
    const float area_t = tw * th;

    float iou0 = 0.0f, iou1 = 0.0f;
    #pragma unroll
    for (int b = 0; b < 2; b++) {
        const float* q = p + 5 * b;
        const float px = q[0] * invS, py = q[1] * invS;
        const float pw = q[2], ph = q[3];
        const float lx = fmaxf(px - 0.5f * pw, tx0);
        const float rx = fminf(px + 0.5f * pw, tx1);
        const float ly = fmaxf(py - 0.5f * ph, ty0);
        const float ry = fminf(py + 0.5f * ph, ty1);
        const float wx = fmaxf(rx - lx, 0.0f);
        const float wy = fmaxf(ry - ly, 0.0f);
        const float inter = wx * wy;
        const float uni = fmaxf(pw * ph + area_t - inter, 1e-10f);
        const float iou = inter / uni;
        if (b == 0) iou0 = iou; else iou1 = iou;
    }
    // jnp.argmax picks first max -> box 1 only on strict greater.
    const int rb = (iou1 > iou0) ? 1 : 0;
    const float miou = fmaxf(iou0, iou1);

    const float* q  = p + 5 * rb;
    const float* tq = t + 5 * rb;
    const float dx = q[0] - tq[0];
    const float dy = q[1] - tq[1];
    const float lxy = dx * dx + dy * dy;
    const float dw = sqrtf(q[2]) - sqrtf(tq[2]);
    const float dh = sqrtf(q[3]) - sqrtf(tq[3]);
    const float lwh = dw * dw + dh * dh;
    const float dob = q[4] - miou;
    const float lobj = dob * dob;

    return obj * (5.0f * (lxy + lwh) + lobj + cls)
         + 0.5f * (1.0f - obj) * noobj;
}

__global__ __launch_bounds__(NTHREADS) void yolo_loss_kernel(
    const float* __restrict__ pred,
    const float* __restrict__ targ,
    int total_cells,
    float* __restrict__ out,
    double inv_bs)
{
    extern __shared__ float smem[];
    __shared__ __align__(8) uint64_t mbar_storage[STAGES];
    __shared__ float warp_sums[NTHREADS / 32];

    const int tid = threadIdx.x;
    const uint32_t smem_u32 = (uint32_t)__cvta_generic_to_shared(smem);
    const uint32_t mbar0 = (uint32_t)__cvta_generic_to_shared(mbar_storage);
    const char* predc = (const char*)pred;
    const char* targc = (const char*)targ;

    const int ntiles = total_cells / TILE;
    const int rem = total_cells - ntiles * TILE;

    // Contiguous ownership: CTA b gets tiles [start, start+count).
    const int q = ntiles / (int)gridDim.x;
    const int r = ntiles % (int)gridDim.x;
    const int b = blockIdx.x;
    const long long start = (long long)b * q + (b < r ? b : r);
    const int count = q + (b < r ? 1 : 0);

    if (tid == 0) {
        #pragma unroll
        for (int s = 0; s < STAGES; s++) mbar_init(mbar0 + 8u * s, 1u);
    }
    __syncthreads();

    // Prologue: issue tiles start..start+2 into stages 0..2 (sequential).
    if (tid == 0) {
        #pragma unroll
        for (int j = 0; j < STAGES - 1; j++) {
            if (j < count)
                issue_tile_bulk(smem_u32, j, mbar0 + 8u * j, predc, targc, start + j);
        }
    }

    float loss = 0.0f;
    unsigned int ph = 0;   // per-stage parity bitmask
    for (int k = 0; k < count; k++) {
        const int s = k & (STAGES - 1);

        // Issue tile start+k+3 into stage (k+3)&3 == (k-1)&3, fully read by
        // all threads before iteration k-1's end barrier.
        if (tid == 0) {
            const int kn = k + (STAGES - 1);
            if (kn < count) {
                const int sn = kn & (STAGES - 1);
                issue_tile_bulk(smem_u32, sn, mbar0 + 8u * sn, predc, targc,
                                start + kn);
            }
        }

        // Wait for this stage's tile.
        mbar_wait(mbar0 + 8u * s, (ph >> s) & 1u);
        ph ^= 1u << s;

        if (tid < TILE) {
            const float* p  = smem + s * STAGE_FLOATS + tid * CH;
            const float* tt = smem + s * STAGE_FLOATS + SFLOATS + tid * CH;
            loss += cell_loss(p, tt);
        }

        __syncthreads();   // single barrier per tile: frees stage for reuse
    }

    // Tail cells (total_cells % TILE), block 0 straight from gmem.
    if (rem && blockIdx.x == 0 && tid < rem) {
        const long long c = (long long)ntiles * TILE + tid;
        loss += cell_loss(pred + c * CH, targ + c * CH);
    }

    // Block reduction
    #pragma unroll
    for (int o = 16; o > 0; o >>= 1)
        loss += __shfl_xor_sync(0xffffffffu, loss, o);
    if ((tid & 31) == 0) warp_sums[tid >> 5] = loss;
    __syncthreads();

    if (tid == 0) {
        const float bsum = warp_sums[0] + warp_sums[1] + warp_sums[2] + warp_sums[3];
        atomicAdd(&g_acc, (double)bsum);
        __threadfence();
        const unsigned int ticket = atomicAdd(&g_counter, 1u);
        if (ticket == gridDim.x - 1u) {
            const double total = atomicAdd(&g_acc, 0.0);
            out[0] = (float)(total * inv_bs);
            g_acc = 0.0;          // reset for next graph replay
            __threadfence();
            g_counter = 0u;
        }
    }
}

extern "C" void kernel_launch(void* const* d_in, const int* in_sizes, int n_in,
                              void* d_out, int out_size) {
    const float* pred = (const float*)d_in[0];
    const float* targ = (const float*)d_in[1];
    const long long n = (long long)in_sizes[0];
    const int total_cells = (int)(n / CH);            // bs * 49
    const int bs = total_cells / (S_GRID * S_GRID);
    const int ntiles = total_cells / TILE;

    int grid = ntiles < MAX_BLOCKS ? ntiles : MAX_BLOCKS;
    if (grid < 1) grid = 1;

    cudaFuncSetAttribute(yolo_loss_kernel,
                         cudaFuncAttributeMaxDynamicSharedMemorySize, SMEM_BYTES);
    yolo_loss_kernel<<<grid, NTHREADS, SMEM_BYTES>>>(pred, targ, total_cells,
                                                     (float*)d_out,
                                                     1.0 / (double)bs);
}

// round 10
// speedup vs baseline: 1.2867x; 1.2867x over previous
#include <cuda_runtime.h>
#include <cstdint>

// YOLO loss: pred/target (bs, 7, 7, 30) f32 -> scalar f32.
// R6 pipeline (grid-strided cp.async.bulk ring, single-thread issue, mbarrier
// completion, one __syncthreads per tile, last-block finalize) retuned to
// TILE=128 / 3 stages: same smem footprint, 25% fewer per-tile overheads.

#define S_GRID 7
#define CH 30
#define TILE 128
#define NTHREADS 128
#define STAGES 3
#define SFLOATS (TILE * CH)                 // 3840 floats per tensor per stage
#define STAGE_FLOATS (2 * SFLOATS)          // 7680 floats (pred + targ)
#define STAGE_BYTES (STAGE_FLOATS * 4)      // 30720 B
#define HALF_BYTES (SFLOATS * 4)            // 15360 B
#define SMEM_BYTES (STAGES * STAGE_BYTES)   // 92160 B -> 2 CTAs/SM
#define MAX_BLOCKS 296                      // 2 * 148

__device__ double g_acc = 0.0;
__device__ unsigned int g_counter = 0u;

__device__ __forceinline__ void mbar_init(uint32_t mbar, uint32_t cnt) {
    asm volatile("mbarrier.init.shared.b64 [%0], %1;" :: "r"(mbar), "r"(cnt) : "memory");
}
__device__ __forceinline__ void mbar_expect_tx(uint32_t mbar, uint32_t bytes) {
    asm volatile("mbarrier.arrive.expect_tx.shared.b64 _, [%0], %1;"
                 :: "r"(mbar), "r"(bytes) : "memory");
}
__device__ __forceinline__ void mbar_wait(uint32_t mbar, uint32_t parity) {
    asm volatile(
        "{\n\t"
        ".reg .pred P;\n\t"
        "WAIT_%=:\n\t"
        "mbarrier.try_wait.parity.acquire.cta.shared::cta.b64 P, [%0], %1, 0x989680;\n\t"
        "@P bra.uni DONE_%=;\n\t"
        "bra.uni WAIT_%=;\n\t"
        "DONE_%=:\n\t"
        "}" :: "r"(mbar), "r"(parity) : "memory");
}
__device__ __forceinline__ void bulk_g2s(uint32_t dst, const void* src,
                                         uint32_t bytes, uint32_t mbar) {
    asm volatile(
        "cp.async.bulk.shared::cta.global.mbarrier::complete_tx::bytes [%0], [%1], %2, [%3];"
        :: "r"(dst), "l"(src), "r"(bytes), "r"(mbar) : "memory");
}

// Issue one tile (pred+targ halves) into a stage; called by tid 0 only.
__device__ __forceinline__ void issue_tile_bulk(uint32_t smem_u32, int stage,
                                                uint32_t mbar,
                                                const char* __restrict__ pred,
                                                const char* __restrict__ targ,
                                                long long tile) {
    const uint32_t dst = smem_u32 + (uint32_t)stage * STAGE_BYTES;
    mbar_expect_tx(mbar, STAGE_BYTES);
    bulk_g2s(dst,              pred + tile * (long long)HALF_BYTES, HALF_BYTES, mbar);
    bulk_g2s(dst + HALF_BYTES, targ + tile * (long long)HALF_BYTES, HALF_BYTES, mbar);
}

// Per-cell loss; p/t point at 30 contiguous floats (smem or gmem).
__device__ __forceinline__ float cell_loss(const float* __restrict__ p,
                                           const float* __restrict__ t)
{
    const float obj = (t[4] > 0.0f) ? 1.0f : 0.0f;

    const float dn0 = p[4] - t[4];
    const float dn1 = p[9] - t[9];
    const float noobj = dn0 * dn0 + dn1 * dn1;

    float cls = 0.0f;
    #pragma unroll
    for (int k = 10; k < 30; k++) {
        const float d = p[k] - t[k];
        cls = fmaf(d, d, cls);
    }

    const float invS = 1.0f / (float)S_GRID;
    const float tx = t[0] * invS, ty = t[1] * invS;
    const float tw = t[2], th = t[3];
    const float tx0 = tx - 0.5f * tw, tx1 = tx + 0.5f * tw;
    const float ty0 = ty - 0.5f * th, ty1 = ty + 0.5f * th;
    const float area_t = tw * th;

    float iou0 = 0.0f, iou1 = 0.0f;
    #pragma unroll
    for (int b = 0; b < 2; b++) {
        const float* q = p + 5 * b;
        const float px = q[0] * invS, py = q[1] * invS;
        const float pw = q[2], ph = q[3];
        const float lx = fmaxf(px - 0.5f * pw, tx0);
        const float rx = fminf(px + 0.5f * pw, tx1);
        const float ly = fmaxf(py - 0.5f * ph, ty0);
        const float ry = fminf(py + 0.5f * ph, ty1);
        const float wx = fmaxf(rx - lx, 0.0f);
        const float wy = fmaxf(ry - ly, 0.0f);
        const float inter = wx * wy;
        const float uni = fmaxf(pw * ph + area_t - inter, 1e-10f);
        const float iou = inter / uni;
        if (b == 0) iou0 = iou; else iou1 = iou;
    }
    // jnp.argmax picks first max -> box 1 only on strict greater.
    const int rb = (iou1 > iou0) ? 1 : 0;
    const float miou = fmaxf(iou0, iou1);

    const float* q  = p + 5 * rb;
    const float* tq = t + 5 * rb;
    const float dx = q[0] - tq[0];
    const float dy = q[1] - tq[1];
    const float lxy = dx * dx + dy * dy;
    const float dw = sqrtf(q[2]) - sqrtf(tq[2]);
    const float dh = sqrtf(q[3]) - sqrtf(tq[3]);
    const float lwh = dw * dw + dh * dh;
    const float dob = q[4] - miou;
    const float lobj = dob * dob;

    return obj * (5.0f * (lxy + lwh) + lobj + cls)
         + 0.5f * (1.0f - obj) * noobj;
}

__global__ __launch_bounds__(NTHREADS) void yolo_loss_kernel(
    const float* __restrict__ pred,
    const float* __restrict__ targ,
    int total_cells,
    float* __restrict__ out,
    double inv_bs)
{
    extern __shared__ float smem[];
    __shared__ __align__(8) uint64_t mbar_storage[STAGES];
    __shared__ float warp_sums[NTHREADS / 32];

    const int tid = threadIdx.x;
    const uint32_t smem_u32 = (uint32_t)__cvta_generic_to_shared(smem);
    const uint32_t mbar0 = (uint32_t)__cvta_generic_to_shared(mbar_storage);
    const char* predc = (const char*)pred;
    const char* targc = (const char*)targ;

    const int ntiles = total_cells / TILE;
    const int rem = total_cells - ntiles * TILE;
    const long long stride = gridDim.x;

    if (tid == 0) {
        #pragma unroll
        for (int s = 0; s < STAGES; s++) mbar_init(mbar0 + 8u * s, 1u);
    }
    __syncthreads();

    // Prologue: issue tiles t0, t0+g into stages 0,1 (grid-strided).
    const long long t0 = blockIdx.x;
    if (tid == 0) {
        #pragma unroll
        for (int j = 0; j < STAGES - 1; j++) {
            const long long tj = t0 + j * stride;
            if (tj < ntiles)
                issue_tile_bulk(smem_u32, j, mbar0 + 8u * j, predc, targc, tj);
        }
    }

    float loss = 0.0f;
    unsigned int ph = 0;   // per-stage parity bitmask
    int s = 0;             // stage = k % STAGES
    for (long long t = t0; t < ntiles; t += stride) {
        // Issue tile t+2g into stage (s+2)%3 == stage of iteration k-1,
        // which all threads finished reading before k-1's end barrier.
        if (tid == 0) {
            const long long tn = t + (STAGES - 1) * stride;
            if (tn < ntiles) {
                int sn = s + (STAGES - 1); if (sn >= STAGES) sn -= STAGES;
                issue_tile_bulk(smem_u32, sn, mbar0 + 8u * sn, predc, targc, tn);
            }
        }

        // Wait for this stage's tile.
        mbar_wait(mbar0 + 8u * s, (ph >> s) & 1u);
        ph ^= 1u << s;

        {
            const float* p  = smem + s * STAGE_FLOATS + tid * CH;
            const float* tt = smem + s * STAGE_FLOATS + SFLOATS + tid * CH;
            loss += cell_loss(p, tt);
        }

        __syncthreads();   // single barrier per tile: frees stage for reuse
        if (++s == STAGES) s = 0;
    }

    // Tail cells (total_cells % TILE; zero at bench shape), block 0 from gmem.
    if (rem && blockIdx.x == 0 && tid < rem) {
        const long long c = (long long)ntiles * TILE + tid;
        loss += cell_loss(pred + c * CH, targ + c * CH);
    }

    // Block reduction
    #pragma unroll
    for (int o = 16; o > 0; o >>= 1)
        loss += __shfl_xor_sync(0xffffffffu, loss, o);
    if ((tid & 31) == 0) warp_sums[tid >> 5] = loss;
    __syncthreads();

    if (tid == 0) {
        const float bsum = warp_sums[0] + warp_sums[1] + warp_sums[2] + warp_sums[3];
        atomicAdd(&g_acc, (double)bsum);
        __threadfence();
        const unsigned int ticket = atomicAdd(&g_counter, 1u);
        if (ticket == gridDim.x - 1u) {
            const double total = atomicAdd(&g_acc, 0.0);
            out[0] = (float)(total * inv_bs);
            g_acc = 0.0;          // reset for next graph replay
            __threadfence();
            g_counter = 0u;
        }
    }
}

extern "C" void kernel_launch(void* const* d_in, const int* in_sizes, int n_in,
                              void* d_out, int out_size) {
    const float* pred = (const float*)d_in[0];
    const float* targ = (const float*)d_in[1];
    const long long n = (long long)in_sizes[0];
    const int total_cells = (int)(n / CH);            // bs * 49
    const int bs = total_cells / (S_GRID * S_GRID);
    const int ntiles = total_cells / TILE;

    int grid = ntiles < MAX_BLOCKS ? ntiles : MAX_BLOCKS;
    if (grid < 1) grid = 1;

    cudaFuncSetAttribute(yolo_loss_kernel,
                         cudaFuncAttributeMaxDynamicSharedMemorySize, SMEM_BYTES);
    yolo_loss_kernel<<<grid, NTHREADS, SMEM_BYTES>>>(pred, targ, total_cells,
                                                     (float*)d_out,
                                                     1.0 / (double)bs);
}